// round 11
// baseline (speedup 1.0000x reference)
#include <cuda_runtime.h>
#include <cuda_bf16.h>
#include <cstdint>
#include <cstddef>

typedef __nv_bfloat16 bf16;

#define BATCH 8
#define CH    256
#define NTOK  4096
#define NG    32
#define CPG   8
#define GEPS  1e-5f

// ---------------- scratch (__device__ globals: allocation-free rule) --------
__device__ bf16  g_h  [(size_t)BATCH * NTOK * CH];   // GN output, [b][n][c]
__device__ bf16  g_q  [(size_t)BATCH * NTOK * CH];   // [b][n][c]
__device__ bf16  g_k  [(size_t)BATCH * NTOK * CH];   // [b][n][c]
__device__ bf16  g_vT [(size_t)BATCH * CH * NTOK];   // [b][c][n]
__device__ bf16  g_att[(size_t)BATCH * NTOK * CH];   // attention output [b][n][c]
__device__ bf16  g_w  [4 * CH * CH];                 // wq, wk, wv, wp as bf16
__device__ float g_mean[BATCH * NG];
__device__ float g_rstd[BATCH * NG];

// ---------------- cp.async / ldmatrix / mma helpers -------------------------
__device__ __forceinline__ void cpa16(void* smem, const void* gmem) {
    uint32_t s = (uint32_t)__cvta_generic_to_shared(smem);
    asm volatile("cp.async.cg.shared.global [%0], [%1], 16;\n" :: "r"(s), "l"(gmem));
}
__device__ __forceinline__ void cpa_commit() {
    asm volatile("cp.async.commit_group;\n");
}
template<int N> __device__ __forceinline__ void cpa_wait() {
    asm volatile("cp.async.wait_group %0;\n" :: "n"(N));
}

__device__ __forceinline__ void ldsm_x4(uint32_t* r, const void* p) {
    uint32_t a = (uint32_t)__cvta_generic_to_shared(p);
    asm volatile("ldmatrix.sync.aligned.m8n8.x4.shared.b16 {%0,%1,%2,%3}, [%4];\n"
        : "=r"(r[0]), "=r"(r[1]), "=r"(r[2]), "=r"(r[3]) : "r"(a));
}

__device__ __forceinline__ void mma_bf16(float* c, const uint32_t a0, const uint32_t a1,
                                         const uint32_t a2, const uint32_t a3,
                                         const uint32_t b0, const uint32_t b1) {
    asm volatile(
        "mma.sync.aligned.m16n8k16.row.col.f32.bf16.bf16.f32 "
        "{%0,%1,%2,%3}, {%4,%5,%6,%7}, {%8,%9}, {%0,%1,%2,%3};\n"
        : "+f"(c[0]), "+f"(c[1]), "+f"(c[2]), "+f"(c[3])
        : "r"(a0), "r"(a1), "r"(a2), "r"(a3), "r"(b0), "r"(b1));
}

// ---------------- GroupNorm stats -------------------------------------------
__global__ void gn_stats(const float* __restrict__ x) {
    int b = blockIdx.x / NG, gid = blockIdx.x % NG;
    const float* base = x + ((size_t)b * CH + gid * CPG) * NTOK;
    const int total = CPG * NTOK;            // 32768
    const float4* p = (const float4*)base;
    float s = 0.f, ss = 0.f;
    for (int i = threadIdx.x; i < total / 4; i += blockDim.x) {
        float4 v = p[i];
        s  += v.x + v.y + v.z + v.w;
        ss += v.x * v.x + v.y * v.y + v.z * v.z + v.w * v.w;
    }
    __shared__ float shm[64];
    #pragma unroll
    for (int o = 16; o; o >>= 1) {
        s  += __shfl_xor_sync(0xffffffffu, s, o);
        ss += __shfl_xor_sync(0xffffffffu, ss, o);
    }
    int w = threadIdx.x >> 5;
    if ((threadIdx.x & 31) == 0) { shm[w] = s; shm[32 + w] = ss; }
    __syncthreads();
    if (threadIdx.x < 32) {
        int nw = blockDim.x >> 5;
        s  = threadIdx.x < nw ? shm[threadIdx.x] : 0.f;
        ss = threadIdx.x < nw ? shm[32 + threadIdx.x] : 0.f;
        #pragma unroll
        for (int o = 16; o; o >>= 1) {
            s  += __shfl_xor_sync(0xffffffffu, s, o);
            ss += __shfl_xor_sync(0xffffffffu, ss, o);
        }
        if (threadIdx.x == 0) {
            float m   = s / (float)total;
            float var = ss / (float)total - m * m;
            g_mean[blockIdx.x] = m;
            g_rstd[blockIdx.x] = rsqrtf(var + GEPS);
        }
    }
}

// ---------------- GroupNorm apply + transpose to [b][n][c] bf16 -------------
__global__ void gn_apply(const float* __restrict__ x,
                         const float* __restrict__ sc,
                         const float* __restrict__ bi) {
    __shared__ float tile[32][33];
    int b  = blockIdx.z;
    int c0 = blockIdx.y * 32, n0 = blockIdx.x * 32;
    int tx = threadIdx.x, ty = threadIdx.y;   // 32 x 8
    #pragma unroll
    for (int j = 0; j < 4; j++) {
        int c = c0 + ty + j * 8;
        float m = g_mean[b * NG + (c >> 3)];
        float r = g_rstd[b * NG + (c >> 3)];
        float v = x[((size_t)b * CH + c) * NTOK + n0 + tx];
        tile[ty + j * 8][tx] = (v - m) * r * sc[c] + bi[c];
    }
    __syncthreads();
    #pragma unroll
    for (int j = 0; j < 4; j++) {
        int n = n0 + ty + j * 8;
        int c = c0 + tx;
        g_h[((size_t)b * NTOK + n) * CH + c] = __float2bfloat16(tile[tx][ty + j * 8]);
    }
}

// ---------------- weight conversion fp32 -> bf16 ----------------------------
__global__ void conv_w(const float* __restrict__ wq, const float* __restrict__ wk,
                       const float* __restrict__ wv, const float* __restrict__ wp) {
    int i = blockIdx.x * blockDim.x + threadIdx.x;
    if (i < CH * CH) {
        g_w[i]               = __float2bfloat16(wq[i]);
        g_w[CH * CH + i]     = __float2bfloat16(wk[i]);
        g_w[2 * CH * CH + i] = __float2bfloat16(wv[i]);
        g_w[3 * CH * CH + i] = __float2bfloat16(wp[i]);
    }
}

// ---------------- generic TN GEMM (TBK=32, double-buffered, ldmatrix) -------
#define TBM 128
#define TBN 128
#define TBK 32
#define SPAD 8
#define GSTR (TBK + SPAD)    // 40 elems = 80 B row stride (16B-divisible)

#define MODE_ROW 0   // bf16 store out[m*ldo + n] (+bias[n])
#define MODE_COL 1   // bf16 store out[n*ldo + m] (+bias[n])
#define MODE_RES 2   // f32  store out[n*ldo + m] = x[n*ldo+m] + acc + bias[n]

__global__ __launch_bounds__(256, 2) void gemm_tn(
    const bf16* __restrict__ A, const bf16* __restrict__ Bm,
    bf16* outb, float* outf,
    const float* __restrict__ bias, const float* __restrict__ resid,
    float alpha, int M, int N, int K,
    size_t strideA, size_t strideB, size_t strideO, size_t strideX,
    int ldo, int mode)
{
    __shared__ bf16 sA[2][TBM][GSTR];
    __shared__ bf16 sB[2][TBN][GSTR];

    int b = blockIdx.z;
    const bf16* Ab = A + (size_t)b * strideA + (size_t)blockIdx.y * TBM * K;
    const bf16* Bb = Bm + (size_t)b * strideB + (size_t)blockIdx.x * TBN * K;

    int tid  = threadIdx.x;
    int lane = tid & 31, warp = tid >> 5;
    int wm = warp >> 2, wn = warp & 3;       // 2 x 4 warps, warp tile 64(M) x 32(N)
    int g  = lane >> 2, tig = lane & 3;
    int lm = lane >> 3, li = lane & 7;       // ldmatrix lane roles

    int lrow = tid >> 2;            // 0..63 (+64 second half)
    int lc8  = (tid & 3) << 3;

    float acc[4][4][4];
    #pragma unroll
    for (int i = 0; i < 4; i++)
        #pragma unroll
        for (int j = 0; j < 4; j++)
            #pragma unroll
            for (int q = 0; q < 4; q++) acc[i][j][q] = 0.f;

    #pragma unroll
    for (int r = 0; r < 2; r++) {
        int row = lrow + r * 64;
        cpa16(&sA[0][row][lc8], Ab + (size_t)row * K + lc8);
        cpa16(&sB[0][row][lc8], Bb + (size_t)row * K + lc8);
    }
    cpa_commit();

    int nk = K / TBK;
    for (int t = 0; t < nk; t++) {
        int buf = t & 1;
        if (t + 1 < nk) {
            int kt = (t + 1) * TBK;
            #pragma unroll
            for (int r = 0; r < 2; r++) {
                int row = lrow + r * 64;
                cpa16(&sA[buf ^ 1][row][lc8], Ab + (size_t)row * K + kt + lc8);
                cpa16(&sB[buf ^ 1][row][lc8], Bb + (size_t)row * K + kt + lc8);
            }
            cpa_commit();
            cpa_wait<1>();
        } else {
            cpa_wait<0>();
        }
        __syncthreads();

        #pragma unroll
        for (int kk = 0; kk < 2; kk++) {
            uint32_t af[4][4];
            #pragma unroll
            for (int mi = 0; mi < 4; mi++)
                ldsm_x4(af[mi],
                        &sA[buf][wm * 64 + mi * 16 + (lm & 1) * 8 + li]
                               [kk * 16 + (lm >> 1) * 8]);
            uint32_t bfr[2][4];
            #pragma unroll
            for (int j = 0; j < 2; j++)
                ldsm_x4(bfr[j],
                        &sB[buf][wn * 32 + j * 16 + (lm >> 1) * 8 + li]
                               [kk * 16 + (lm & 1) * 8]);
            #pragma unroll
            for (int mi = 0; mi < 4; mi++)
                #pragma unroll
                for (int ni = 0; ni < 4; ni++)
                    mma_bf16(acc[mi][ni], af[mi][0], af[mi][1], af[mi][2], af[mi][3],
                             bfr[ni >> 1][(ni & 1) * 2], bfr[ni >> 1][(ni & 1) * 2 + 1]);
        }
        __syncthreads();
    }

    // -------- epilogue --------
    #pragma unroll
    for (int mi = 0; mi < 4; mi++) {
        #pragma unroll
        for (int ni = 0; ni < 4; ni++) {
            int row = blockIdx.y * TBM + wm * 64 + mi * 16 + g;
            int col = blockIdx.x * TBN + wn * 32 + ni * 8 + tig * 2;
            float v0 = acc[mi][ni][0] * alpha;
            float v1 = acc[mi][ni][1] * alpha;
            float v2 = acc[mi][ni][2] * alpha;
            float v3 = acc[mi][ni][3] * alpha;
            if (bias) {
                float b0 = bias[col], b1 = bias[col + 1];
                v0 += b0; v1 += b1; v2 += b0; v3 += b1;
            }
            if (mode == MODE_ROW) {
                bf16* o = outb + (size_t)b * strideO + (size_t)row * ldo + col;
                *(__nv_bfloat162*)o = __floats2bfloat162_rn(v0, v1);
                *(__nv_bfloat162*)(o + (size_t)8 * ldo) = __floats2bfloat162_rn(v2, v3);
            } else if (mode == MODE_COL) {
                bf16* o = outb + (size_t)b * strideO;
                o[(size_t)col * ldo + row]           = __float2bfloat16(v0);
                o[(size_t)(col + 1) * ldo + row]     = __float2bfloat16(v1);
                o[(size_t)col * ldo + row + 8]       = __float2bfloat16(v2);
                o[(size_t)(col + 1) * ldo + row + 8] = __float2bfloat16(v3);
            } else {
                float* o = outf + (size_t)b * strideO;
                const float* xr = resid + (size_t)b * strideX;
                size_t i00 = (size_t)col * ldo + row;
                size_t i10 = (size_t)(col + 1) * ldo + row;
                o[i00]     = xr[i00]     + v0;
                o[i10]     = xr[i10]     + v1;
                o[i00 + 8] = xr[i00 + 8] + v2;
                o[i10 + 8] = xr[i10 + 8] + v3;
            }
        }
    }
}

// ---------------- fused flash attention (64x64 tiles, 2 CTAs/SM) ------------
// 128 threads (4 warps), warp w owns Q rows [w*16, w*16+16). 64 KV iterations.
// Fixed-shift softmax (exact after normalization). smem = 102 KB -> 2 CTAs/SM
// so a second CTA's MMAs fill the tensor pipe during softmax/barriers.
#define FA_BM 64
#define FA_BN 64
#define FA_D  256
#define FA_IT (NTOK / FA_BN)      // 64
#define QSTR  (FA_D + 8)          // 264 elems = 528 B
#define VSTR  (FA_BN + 8)         // 72 elems = 144 B
#define FA_C1 0.09016844f         // (1/16) * log2(e)
#define FA_C2 -17.3123404906676f  // -12 * log2(e)

// 64 rows x 256 cols bf16 tile (2048 x 16B chunks, 128 threads -> 16 each)
__device__ __forceinline__ void fa_load_qk(bf16* s, const bf16* gsrc, int tid) {
    #pragma unroll
    for (int t = 0; t < 16; t++) {
        int idx = t * 128 + tid;       // 0..2047
        int r = idx >> 5;              // 0..63
        int c = (idx & 31) << 3;       // 0..248
        cpa16(s + r * QSTR + c, gsrc + (size_t)r * FA_D + c);
    }
}
// 256 rows x 64 cols bf16 tile (2048 x 16B chunks)
__device__ __forceinline__ void fa_load_v(bf16* s, const bf16* gsrc, int tid) {
    #pragma unroll
    for (int t = 0; t < 16; t++) {
        int idx = t * 128 + tid;       // 0..2047
        int r = idx >> 3;              // 0..255
        int c = (idx & 7) << 3;        // 0..56
        cpa16(s + r * VSTR + c, gsrc + (size_t)r * NTOK + c);
    }
}

__global__ __launch_bounds__(128, 2) void fa_kernel(
    const bf16* __restrict__ Qg,    // [b][n][c]
    const bf16* __restrict__ Kg,    // [b][n][c]
    const bf16* __restrict__ Vt,    // [b][c][n]
    bf16* __restrict__ Og)          // [b][n][c]
{
    extern __shared__ bf16 fsm[];
    bf16* sQ = fsm;                       // [64][QSTR]
    bf16* sK = sQ + FA_BM * QSTR;         // [64][QSTR]
    bf16* sV = sK + FA_BM * QSTR;         // [256][VSTR]

    const int b = blockIdx.y;
    const int qblk = blockIdx.x;

    const bf16* Qb = Qg + ((size_t)b * NTOK + (size_t)qblk * FA_BM) * FA_D;
    const bf16* Kb = Kg + (size_t)b * NTOK * FA_D;
    const bf16* Vb = Vt + (size_t)b * FA_D * NTOK;

    const int tid = threadIdx.x;
    const int lane = tid & 31, w = tid >> 5;      // 4 warps
    const int g = lane >> 2, tig = lane & 3;
    const int lm = lane >> 3, li = lane & 7;
    const int r0 = w * 16 + g;            // local Q row (and r0+8)

    // per-lane ldmatrix row bases
    const bf16* qbase = sQ + (w * 16 + (lm & 1) * 8 + li) * QSTR + (lm >> 1) * 8;
    const bf16* kbase = sK + ((lm >> 1) * 8 + li) * QSTR + (lm & 1) * 8;
    const bf16* vbase = sV + ((lm >> 1) * 8 + li) * VSTR + (lm & 1) * 8;

    // prologue: group1 = Q + K0, group2 = V0
    fa_load_qk(sQ, Qb, tid);
    fa_load_qk(sK, Kb, tid);
    cpa_commit();
    fa_load_v(sV, Vb, tid);
    cpa_commit();

    float oacc[32][4];
    #pragma unroll
    for (int i = 0; i < 32; i++)
        #pragma unroll
        for (int q = 0; q < 4; q++) oacc[i][q] = 0.f;
    float l0 = 0.f, l1 = 0.f;   // per-thread partial row sums

    for (int it = 0; it < FA_IT; it++) {
        // ---- wait Q/K_it (V_it may still be in flight) ----
        cpa_wait<1>();
        __syncthreads();

        // ---- S = Q K^T over D=256 (64 kv cols -> 8 n-frags) ----
        float sacc[8][4];
        #pragma unroll
        for (int i = 0; i < 8; i++)
            #pragma unroll
            for (int q = 0; q < 4; q++) sacc[i][q] = 0.f;

        #pragma unroll
        for (int ks = 0; ks < 16; ks++) {
            uint32_t a[4];
            ldsm_x4(a, qbase + ks * 16);
            #pragma unroll
            for (int j = 0; j < 4; j++) {
                uint32_t bf4[4];
                ldsm_x4(bf4, kbase + j * 16 * QSTR + ks * 16);
                mma_bf16(sacc[2 * j],     a[0], a[1], a[2], a[3], bf4[0], bf4[1]);
                mma_bf16(sacc[2 * j + 1], a[0], a[1], a[2], a[3], bf4[2], bf4[3]);
            }
        }
        __syncthreads();   // all warps done reading sK

        // ---- prefetch K_{it+1} ----
        if (it + 1 < FA_IT) {
            fa_load_qk(sK, Kb + (size_t)(it + 1) * FA_BN * FA_D, tid);
            cpa_commit();
        }

        // ---- fixed-shift softmax numerator: P = exp2(s*c1 + c2) ----
        uint32_t pk[8][2];
        #pragma unroll
        for (int ni = 0; ni < 8; ni++) {
            float e0 = exp2f(fmaf(sacc[ni][0], FA_C1, FA_C2));
            float e1 = exp2f(fmaf(sacc[ni][1], FA_C1, FA_C2));
            float e2 = exp2f(fmaf(sacc[ni][2], FA_C1, FA_C2));
            float e3 = exp2f(fmaf(sacc[ni][3], FA_C1, FA_C2));
            l0 += e0 + e1; l1 += e2 + e3;
            __nv_bfloat162 p01 = __floats2bfloat162_rn(e0, e1);
            __nv_bfloat162 p23 = __floats2bfloat162_rn(e2, e3);
            pk[ni][0] = *(uint32_t*)&p01;
            pk[ni][1] = *(uint32_t*)&p23;
        }

        // ---- wait V_it ----
        if (it + 1 < FA_IT) cpa_wait<1>(); else cpa_wait<0>();
        __syncthreads();

        // ---- O += P @ V (contract over 64 kv, Vt layout [c][kv]) ----
        #pragma unroll
        for (int kk = 0; kk < 4; kk++) {
            uint32_t a0 = pk[2 * kk][0];
            uint32_t a1 = pk[2 * kk][1];
            uint32_t a2 = pk[2 * kk + 1][0];
            uint32_t a3 = pk[2 * kk + 1][1];
            #pragma unroll
            for (int j = 0; j < 16; j++) {
                uint32_t bf4[4];
                ldsm_x4(bf4, vbase + j * 16 * VSTR + kk * 16);
                mma_bf16(oacc[2 * j],     a0, a1, a2, a3, bf4[0], bf4[1]);
                mma_bf16(oacc[2 * j + 1], a0, a1, a2, a3, bf4[2], bf4[3]);
            }
        }
        __syncthreads();   // all warps done reading sV

        // ---- prefetch V_{it+1} ----
        if (it + 1 < FA_IT) {
            fa_load_v(sV, Vb + (size_t)(it + 1) * FA_BN, tid);
            cpa_commit();
        }
    }

    // ---- epilogue: reduce l across the quad (tig lanes), O /= l, store ----
    l0 += __shfl_xor_sync(0xffffffffu, l0, 1);
    l0 += __shfl_xor_sync(0xffffffffu, l0, 2);
    l1 += __shfl_xor_sync(0xffffffffu, l1, 1);
    l1 += __shfl_xor_sync(0xffffffffu, l1, 2);
    float i0 = 1.f / l0, i1 = 1.f / l1;
    bf16* orow = Og + ((size_t)b * NTOK + (size_t)qblk * FA_BM + r0) * FA_D;
    #pragma unroll
    for (int ni = 0; ni < 32; ni++) {
        int c = ni * 8 + tig * 2;
        *(__nv_bfloat162*)(orow + c) =
            __floats2bfloat162_rn(oacc[ni][0] * i0, oacc[ni][1] * i0);
        *(__nv_bfloat162*)(orow + (size_t)8 * FA_D + c) =
            __floats2bfloat162_rn(oacc[ni][2] * i1, oacc[ni][3] * i1);
    }
}

// ---------------- launcher ---------------------------------------------------
extern "C" void kernel_launch(void* const* d_in, const int* in_sizes, int n_in,
                              void* d_out, int out_size) {
    const float* x   = (const float*)d_in[0];
    const float* gns = (const float*)d_in[1];
    const float* gnb = (const float*)d_in[2];
    const float* wq  = (const float*)d_in[3];
    const float* bq  = (const float*)d_in[4];
    const float* wk  = (const float*)d_in[5];
    const float* bk  = (const float*)d_in[6];
    const float* wv  = (const float*)d_in[7];
    const float* bv  = (const float*)d_in[8];
    const float* wp  = (const float*)d_in[9];
    const float* bp  = (const float*)d_in[10];
    float* out = (float*)d_out;

    bf16 *p_h, *p_q, *p_k, *p_vT, *p_att, *p_w;
    cudaGetSymbolAddress((void**)&p_h,   g_h);
    cudaGetSymbolAddress((void**)&p_q,   g_q);
    cudaGetSymbolAddress((void**)&p_k,   g_k);
    cudaGetSymbolAddress((void**)&p_vT,  g_vT);
    cudaGetSymbolAddress((void**)&p_att, g_att);
    cudaGetSymbolAddress((void**)&p_w,   g_w);

    const size_t sNC = (size_t)NTOK * CH;
    const size_t sCN = (size_t)CH * NTOK;

    const int fa_smem = (FA_BM * QSTR + FA_BM * QSTR + FA_D * VSTR) * (int)sizeof(bf16);
    cudaFuncSetAttribute(fa_kernel, cudaFuncAttributeMaxDynamicSharedMemorySize, fa_smem);

    // 1) GroupNorm
    gn_stats<<<BATCH * NG, 256>>>(x);
    gn_apply<<<dim3(NTOK / 32, CH / 32, BATCH), dim3(32, 8)>>>(x, gns, gnb);
    conv_w<<<(CH * CH + 255) / 256, 256>>>(wq, wk, wv, wp);

    // 2) Q, K (row-major [N,C]) and V (col-major -> [C,N])
    dim3 gproj(CH / TBN, NTOK / TBM, BATCH);
    gemm_tn<<<gproj, 256>>>(p_h, p_w,               p_q,  nullptr, bq, nullptr,
                            1.f, NTOK, CH, CH, sNC, 0, sNC, 0, CH,   MODE_ROW);
    gemm_tn<<<gproj, 256>>>(p_h, p_w + CH * CH,     p_k,  nullptr, bk, nullptr,
                            1.f, NTOK, CH, CH, sNC, 0, sNC, 0, CH,   MODE_ROW);
    gemm_tn<<<gproj, 256>>>(p_h, p_w + 2 * CH * CH, p_vT, nullptr, bv, nullptr,
                            1.f, NTOK, CH, CH, sNC, 0, sCN, 0, NTOK, MODE_COL);

    // 3) fused attention: softmax(QK^T * C^-0.5) @ V  -> g_att [b][n][c]
    fa_kernel<<<dim3(NTOK / FA_BM, BATCH), 128, fa_smem>>>(p_q, p_k, p_vT, p_att);

    // 4) out = x + hatt @ wp^T + bp   (store transposed into [b][c][n] fp32)
    gemm_tn<<<dim3(CH / TBN, NTOK / TBM, BATCH), 256>>>(
        p_att, p_w + 3 * CH * CH, nullptr, out, bp, x,
        1.f, NTOK, CH, CH, sNC, 0, sCN, sCN, NTOK, MODE_RES);
}

// round 13
// speedup vs baseline: 1.0567x; 1.0567x over previous
#include <cuda_runtime.h>
#include <cuda_bf16.h>
#include <cstdint>
#include <cstddef>

typedef __nv_bfloat16 bf16;

#define BATCH 8
#define CH    256
#define NTOK  4096
#define NG    32
#define CPG   8
#define GEPS  1e-5f

// ---------------- scratch (__device__ globals: allocation-free rule) --------
__device__ bf16  g_h  [(size_t)BATCH * NTOK * CH];   // GN output, [b][n][c]
__device__ bf16  g_q  [(size_t)BATCH * NTOK * CH];   // [b][n][c]
__device__ bf16  g_k  [(size_t)BATCH * NTOK * CH];   // [b][n][c]
__device__ bf16  g_vT [(size_t)BATCH * CH * NTOK];   // [b][c][n]
__device__ bf16  g_att[(size_t)BATCH * NTOK * CH];   // attention output [b][n][c]
__device__ bf16  g_w  [4 * CH * CH];                 // wq, wk, wv, wp as bf16
__device__ float g_mean[BATCH * NG];
__device__ float g_rstd[BATCH * NG];

// ---------------- cp.async / ldmatrix / mma helpers -------------------------
__device__ __forceinline__ void cpa16(void* smem, const void* gmem) {
    uint32_t s = (uint32_t)__cvta_generic_to_shared(smem);
    asm volatile("cp.async.cg.shared.global [%0], [%1], 16;\n" :: "r"(s), "l"(gmem));
}
__device__ __forceinline__ void cpa_commit() {
    asm volatile("cp.async.commit_group;\n");
}
template<int N> __device__ __forceinline__ void cpa_wait() {
    asm volatile("cp.async.wait_group %0;\n" :: "n"(N));
}

__device__ __forceinline__ void ldsm_x4(uint32_t* r, const void* p) {
    uint32_t a = (uint32_t)__cvta_generic_to_shared(p);
    asm volatile("ldmatrix.sync.aligned.m8n8.x4.shared.b16 {%0,%1,%2,%3}, [%4];\n"
        : "=r"(r[0]), "=r"(r[1]), "=r"(r[2]), "=r"(r[3]) : "r"(a));
}

__device__ __forceinline__ void mma_bf16(float* c, const uint32_t a0, const uint32_t a1,
                                         const uint32_t a2, const uint32_t a3,
                                         const uint32_t b0, const uint32_t b1) {
    asm volatile(
        "mma.sync.aligned.m16n8k16.row.col.f32.bf16.bf16.f32 "
        "{%0,%1,%2,%3}, {%4,%5,%6,%7}, {%8,%9}, {%0,%1,%2,%3};\n"
        : "+f"(c[0]), "+f"(c[1]), "+f"(c[2]), "+f"(c[3])
        : "r"(a0), "r"(a1), "r"(a2), "r"(a3), "r"(b0), "r"(b1));
}

// ---------------- GroupNorm stats -------------------------------------------
__global__ void gn_stats(const float* __restrict__ x) {
    int b = blockIdx.x / NG, gid = blockIdx.x % NG;
    const float* base = x + ((size_t)b * CH + gid * CPG) * NTOK;
    const int total = CPG * NTOK;            // 32768
    const float4* p = (const float4*)base;
    float s = 0.f, ss = 0.f;
    for (int i = threadIdx.x; i < total / 4; i += blockDim.x) {
        float4 v = p[i];
        s  += v.x + v.y + v.z + v.w;
        ss += v.x * v.x + v.y * v.y + v.z * v.z + v.w * v.w;
    }
    __shared__ float shm[64];
    #pragma unroll
    for (int o = 16; o; o >>= 1) {
        s  += __shfl_xor_sync(0xffffffffu, s, o);
        ss += __shfl_xor_sync(0xffffffffu, ss, o);
    }
    int w = threadIdx.x >> 5;
    if ((threadIdx.x & 31) == 0) { shm[w] = s; shm[32 + w] = ss; }
    __syncthreads();
    if (threadIdx.x < 32) {
        int nw = blockDim.x >> 5;
        s  = threadIdx.x < nw ? shm[threadIdx.x] : 0.f;
        ss = threadIdx.x < nw ? shm[32 + threadIdx.x] : 0.f;
        #pragma unroll
        for (int o = 16; o; o >>= 1) {
            s  += __shfl_xor_sync(0xffffffffu, s, o);
            ss += __shfl_xor_sync(0xffffffffu, ss, o);
        }
        if (threadIdx.x == 0) {
            float m   = s / (float)total;
            float var = ss / (float)total - m * m;
            g_mean[blockIdx.x] = m;
            g_rstd[blockIdx.x] = rsqrtf(var + GEPS);
        }
    }
}

// ---------------- GroupNorm apply + transpose to [b][n][c] bf16 -------------
__global__ void gn_apply(const float* __restrict__ x,
                         const float* __restrict__ sc,
                         const float* __restrict__ bi) {
    __shared__ float tile[32][33];
    int b  = blockIdx.z;
    int c0 = blockIdx.y * 32, n0 = blockIdx.x * 32;
    int tx = threadIdx.x, ty = threadIdx.y;   // 32 x 8
    #pragma unroll
    for (int j = 0; j < 4; j++) {
        int c = c0 + ty + j * 8;
        float m = g_mean[b * NG + (c >> 3)];
        float r = g_rstd[b * NG + (c >> 3)];
        float v = x[((size_t)b * CH + c) * NTOK + n0 + tx];
        tile[ty + j * 8][tx] = (v - m) * r * sc[c] + bi[c];
    }
    __syncthreads();
    #pragma unroll
    for (int j = 0; j < 4; j++) {
        int n = n0 + ty + j * 8;
        int c = c0 + tx;
        g_h[((size_t)b * NTOK + n) * CH + c] = __float2bfloat16(tile[tx][ty + j * 8]);
    }
}

// ---------------- weight conversion fp32 -> bf16 ----------------------------
__global__ void conv_w(const float* __restrict__ wq, const float* __restrict__ wk,
                       const float* __restrict__ wv, const float* __restrict__ wp) {
    int i = blockIdx.x * blockDim.x + threadIdx.x;
    if (i < CH * CH) {
        g_w[i]               = __float2bfloat16(wq[i]);
        g_w[CH * CH + i]     = __float2bfloat16(wk[i]);
        g_w[2 * CH * CH + i] = __float2bfloat16(wv[i]);
        g_w[3 * CH * CH + i] = __float2bfloat16(wp[i]);
    }
}

// ---------------- generic TN GEMM (TBK=32, double-buffered, ldmatrix) -------
#define TBM 128
#define TBN 128
#define TBK 32
#define SPAD 8
#define GSTR (TBK + SPAD)

#define MODE_ROW 0
#define MODE_COL 1
#define MODE_RES 2

__global__ __launch_bounds__(256, 2) void gemm_tn(
    const bf16* __restrict__ A, const bf16* __restrict__ Bm,
    bf16* outb, float* outf,
    const float* __restrict__ bias, const float* __restrict__ resid,
    float alpha, int M, int N, int K,
    size_t strideA, size_t strideB, size_t strideO, size_t strideX,
    int ldo, int mode)
{
    __shared__ bf16 sA[2][TBM][GSTR];
    __shared__ bf16 sB[2][TBN][GSTR];

    int b = blockIdx.z;
    const bf16* Ab = A + (size_t)b * strideA + (size_t)blockIdx.y * TBM * K;
    const bf16* Bb = Bm + (size_t)b * strideB + (size_t)blockIdx.x * TBN * K;

    int tid  = threadIdx.x;
    int lane = tid & 31, warp = tid >> 5;
    int wm = warp >> 2, wn = warp & 3;
    int g  = lane >> 2, tig = lane & 3;
    int lm = lane >> 3, li = lane & 7;

    int lrow = tid >> 2;
    int lc8  = (tid & 3) << 3;

    float acc[4][4][4];
    #pragma unroll
    for (int i = 0; i < 4; i++)
        #pragma unroll
        for (int j = 0; j < 4; j++)
            #pragma unroll
            for (int q = 0; q < 4; q++) acc[i][j][q] = 0.f;

    #pragma unroll
    for (int r = 0; r < 2; r++) {
        int row = lrow + r * 64;
        cpa16(&sA[0][row][lc8], Ab + (size_t)row * K + lc8);
        cpa16(&sB[0][row][lc8], Bb + (size_t)row * K + lc8);
    }
    cpa_commit();

    int nk = K / TBK;
    for (int t = 0; t < nk; t++) {
        int buf = t & 1;
        if (t + 1 < nk) {
            int kt = (t + 1) * TBK;
            #pragma unroll
            for (int r = 0; r < 2; r++) {
                int row = lrow + r * 64;
                cpa16(&sA[buf ^ 1][row][lc8], Ab + (size_t)row * K + kt + lc8);
                cpa16(&sB[buf ^ 1][row][lc8], Bb + (size_t)row * K + kt + lc8);
            }
            cpa_commit();
            cpa_wait<1>();
        } else {
            cpa_wait<0>();
        }
        __syncthreads();

        #pragma unroll
        for (int kk = 0; kk < 2; kk++) {
            uint32_t af[4][4];
            #pragma unroll
            for (int mi = 0; mi < 4; mi++)
                ldsm_x4(af[mi],
                        &sA[buf][wm * 64 + mi * 16 + (lm & 1) * 8 + li]
                               [kk * 16 + (lm >> 1) * 8]);
            uint32_t bfr[2][4];
            #pragma unroll
            for (int j = 0; j < 2; j++)
                ldsm_x4(bfr[j],
                        &sB[buf][wn * 32 + j * 16 + (lm >> 1) * 8 + li]
                               [kk * 16 + (lm & 1) * 8]);
            #pragma unroll
            for (int mi = 0; mi < 4; mi++)
                #pragma unroll
                for (int ni = 0; ni < 4; ni++)
                    mma_bf16(acc[mi][ni], af[mi][0], af[mi][1], af[mi][2], af[mi][3],
                             bfr[ni >> 1][(ni & 1) * 2], bfr[ni >> 1][(ni & 1) * 2 + 1]);
        }
        __syncthreads();
    }

    #pragma unroll
    for (int mi = 0; mi < 4; mi++) {
        #pragma unroll
        for (int ni = 0; ni < 4; ni++) {
            int row = blockIdx.y * TBM + wm * 64 + mi * 16 + g;
            int col = blockIdx.x * TBN + wn * 32 + ni * 8 + tig * 2;
            float v0 = acc[mi][ni][0] * alpha;
            float v1 = acc[mi][ni][1] * alpha;
            float v2 = acc[mi][ni][2] * alpha;
            float v3 = acc[mi][ni][3] * alpha;
            if (bias) {
                float b0 = bias[col], b1 = bias[col + 1];
                v0 += b0; v1 += b1; v2 += b0; v3 += b1;
            }
            if (mode == MODE_ROW) {
                bf16* o = outb + (size_t)b * strideO + (size_t)row * ldo + col;
                *(__nv_bfloat162*)o = __floats2bfloat162_rn(v0, v1);
                *(__nv_bfloat162*)(o + (size_t)8 * ldo) = __floats2bfloat162_rn(v2, v3);
            } else if (mode == MODE_COL) {
                bf16* o = outb + (size_t)b * strideO;
                o[(size_t)col * ldo + row]           = __float2bfloat16(v0);
                o[(size_t)(col + 1) * ldo + row]     = __float2bfloat16(v1);
                o[(size_t)col * ldo + row + 8]       = __float2bfloat16(v2);
                o[(size_t)(col + 1) * ldo + row + 8] = __float2bfloat16(v3);
            } else {
                float* o = outf + (size_t)b * strideO;
                const float* xr = resid + (size_t)b * strideX;
                size_t i00 = (size_t)col * ldo + row;
                size_t i10 = (size_t)(col + 1) * ldo + row;
                o[i00]     = xr[i00]     + v0;
                o[i10]     = xr[i10]     + v1;
                o[i00 + 8] = xr[i00 + 8] + v2;
                o[i10 + 8] = xr[i10 + 8] + v3;
            }
        }
    }
}

// ---------------- fused flash attention (BN=64, K/V double-buffered, --------
// softmax interleaved with PV). 256 threads, warp w owns Q rows [w*16,w*16+16).
// Fixed-shift softmax (exact after normalization). 64 KV iterations.
// Per iter: prefetch K(i+1),V(i) -> idle buffers; S(i); then exp(i) fused into
// PV(i-1) MMA stream (pkA=P(i-1) consumed, pkB=P(i) produced); 1 sync/iter.
#define FA_BM 128
#define FA_BN 64
#define FA_D  256
#define FA_IT (NTOK / FA_BN)      // 64
#define QSTR  (FA_D + 8)          // 264 elems = 528 B
#define VSTR  (FA_BN + 8)         // 72 elems = 144 B
#define FA_C1 0.09016844f         // (1/16) * log2(e)
#define FA_C2 -17.3123404906676f  // -12 * log2(e)
// smem: Q 128*QSTR + K 2*64*QSTR + V 2*256*VSTR  (elems)
#define FA_SMEM ((256 * QSTR + 512 * VSTR) * (int)sizeof(bf16))   // 208896 B

// 128 rows x 256 cols (gmem row stride FA_D)
__device__ __forceinline__ void fa_load_q(bf16* s, const bf16* g, int tid) {
    #pragma unroll
    for (int t = 0; t < 16; t++) {
        int idx = t * 256 + tid;
        int r = idx >> 5, c = (idx & 31) << 3;
        cpa16(s + r * QSTR + c, g + (size_t)r * FA_D + c);
    }
}
// 64 rows x 256 cols (gmem row stride FA_D)
__device__ __forceinline__ void fa_load_k(bf16* s, const bf16* g, int tid) {
    #pragma unroll
    for (int t = 0; t < 8; t++) {
        int idx = t * 256 + tid;
        int r = idx >> 5, c = (idx & 31) << 3;
        cpa16(s + r * QSTR + c, g + (size_t)r * FA_D + c);
    }
}
// 256 rows x 64 cols (gmem row stride NTOK)
__device__ __forceinline__ void fa_load_v(bf16* s, const bf16* g, int tid) {
    #pragma unroll
    for (int t = 0; t < 8; t++) {
        int idx = t * 256 + tid;
        int r = idx >> 3, c = (idx & 7) << 3;
        cpa16(s + r * VSTR + c, g + (size_t)r * NTOK + c);
    }
}

// S = Q K^T for this warp's 16 rows x 64 kv cols, contracting D=256
__device__ __forceinline__ void fa_s(float (*sacc)[4], const bf16* qb, const bf16* kb) {
    #pragma unroll
    for (int ks = 0; ks < 16; ks++) {
        uint32_t a[4];
        ldsm_x4(a, qb + ks * 16);
        #pragma unroll
        for (int j = 0; j < 4; j++) {
            uint32_t b4[4];
            ldsm_x4(b4, kb + j * 16 * QSTR + ks * 16);
            mma_bf16(sacc[2 * j],     a[0], a[1], a[2], a[3], b4[0], b4[1]);
            mma_bf16(sacc[2 * j + 1], a[0], a[1], a[2], a[3], b4[2], b4[3]);
        }
    }
}

// exp two S fragments -> two packed P fragments (+ row-sum accumulation)
__device__ __forceinline__ void fa_exp2frags(const float* sa, const float* sb,
                                             uint32_t* pa, uint32_t* pb,
                                             float& l0, float& l1) {
    float e0 = exp2f(fmaf(sa[0], FA_C1, FA_C2));
    float e1 = exp2f(fmaf(sa[1], FA_C1, FA_C2));
    float e2 = exp2f(fmaf(sa[2], FA_C1, FA_C2));
    float e3 = exp2f(fmaf(sa[3], FA_C1, FA_C2));
    float f0 = exp2f(fmaf(sb[0], FA_C1, FA_C2));
    float f1 = exp2f(fmaf(sb[1], FA_C1, FA_C2));
    float f2 = exp2f(fmaf(sb[2], FA_C1, FA_C2));
    float f3 = exp2f(fmaf(sb[3], FA_C1, FA_C2));
    l0 += e0 + e1 + f0 + f1;
    l1 += e2 + e3 + f2 + f3;
    __nv_bfloat162 t;
    t = __floats2bfloat162_rn(e0, e1); pa[0] = *(uint32_t*)&t;
    t = __floats2bfloat162_rn(e2, e3); pa[1] = *(uint32_t*)&t;
    t = __floats2bfloat162_rn(f0, f1); pb[0] = *(uint32_t*)&t;
    t = __floats2bfloat162_rn(f2, f3); pb[1] = *(uint32_t*)&t;
}

__global__ __launch_bounds__(256) void fa_kernel(
    const bf16* __restrict__ Qg,    // [b][n][c]
    const bf16* __restrict__ Kg,    // [b][n][c]
    const bf16* __restrict__ Vt,    // [b][c][n]
    bf16* __restrict__ Og)          // [b][n][c]
{
    extern __shared__ bf16 fsm[];
    bf16* sQ = fsm;                                // [128][QSTR]
    bf16* sK0 = sQ + FA_BM * QSTR;                 // [64][QSTR]
    bf16* sK1 = sK0 + FA_BN * QSTR;
    bf16* sV0 = sK1 + FA_BN * QSTR;                // [256][VSTR]
    bf16* sV1 = sV0 + FA_D * VSTR;

    const int b = blockIdx.y;
    const int qblk = blockIdx.x;

    const bf16* Qb = Qg + ((size_t)b * NTOK + (size_t)qblk * FA_BM) * FA_D;
    const bf16* Kb = Kg + (size_t)b * NTOK * FA_D;
    const bf16* Vb = Vt + (size_t)b * FA_D * NTOK;

    const int tid = threadIdx.x;
    const int lane = tid & 31, w = tid >> 5;       // 8 warps
    const int g = lane >> 2, tig = lane & 3;
    const int lm = lane >> 3, li = lane & 7;
    const int r0 = w * 16 + g;

    // per-lane ldmatrix bases
    const bf16* qb = sQ + (w * 16 + (lm & 1) * 8 + li) * QSTR + (lm >> 1) * 8;
    const uint32_t koff = ((lm >> 1) * 8 + li) * QSTR + (lm & 1) * 8;
    const uint32_t voff = ((lm >> 1) * 8 + li) * VSTR + (lm & 1) * 8;
    const bf16* kb[2] = { sK0 + koff, sK1 + koff };
    const bf16* vb[2] = { sV0 + voff, sV1 + voff };
    bf16* sKbuf[2] = { sK0, sK1 };
    bf16* sVbuf[2] = { sV0, sV1 };

    // prologue: G0 = Q + K0 ; G1 = K1 + V0
    fa_load_q(sQ, Qb, tid);
    fa_load_k(sK0, Kb, tid);
    cpa_commit();
    fa_load_k(sK1, Kb + (size_t)FA_BN * FA_D, tid);
    fa_load_v(sV0, Vb, tid);
    cpa_commit();

    float oacc[32][4];
    #pragma unroll
    for (int i = 0; i < 32; i++)
        #pragma unroll
        for (int q = 0; q < 4; q++) oacc[i][q] = 0.f;
    float l0 = 0.f, l1 = 0.f;
    float sacc[8][4];
    uint32_t pkA[8][2], pkB[8][2];

    // ---- iter 0: S(0) + exp(0) -> pkA (no PV yet) ----
    cpa_wait<1>();            // G0 (Q + K0) done
    __syncthreads();
    #pragma unroll
    for (int i = 0; i < 8; i++)
        #pragma unroll
        for (int q = 0; q < 4; q++) sacc[i][q] = 0.f;
    fa_s(sacc, qb, kb[0]);
    #pragma unroll
    for (int kk = 0; kk < 4; kk++)
        fa_exp2frags(sacc[2 * kk], sacc[2 * kk + 1],
                     pkA[2 * kk], pkA[2 * kk + 1], l0, l1);
    cpa_wait<0>();            // G1 (K1 + V0) done
    __syncthreads();

    // ---- main loop: iters 1..63 ----
    for (int i = 1; i < FA_IT; i++) {
        // prefetch into idle buffers (overlaps the whole MMA phase)
        if (i + 1 < FA_IT)
            fa_load_k(sKbuf[(i + 1) & 1], Kb + (size_t)(i + 1) * FA_BN * FA_D, tid);
        fa_load_v(sVbuf[i & 1], Vb + (size_t)i * FA_BN, tid);
        cpa_commit();

        // S(i)
        #pragma unroll
        for (int t = 0; t < 8; t++)
            #pragma unroll
            for (int q = 0; q < 4; q++) sacc[t][q] = 0.f;
        fa_s(sacc, qb, kb[i & 1]);

        // fused: exp(i) -> pkB interleaved with PV(i-1) using pkA
        const bf16* vcur = vb[(i - 1) & 1];
        #pragma unroll
        for (int kk = 0; kk < 4; kk++) {
            fa_exp2frags(sacc[2 * kk], sacc[2 * kk + 1],
                         pkB[2 * kk], pkB[2 * kk + 1], l0, l1);
            uint32_t a0 = pkA[2 * kk][0], a1 = pkA[2 * kk][1];
            uint32_t a2 = pkA[2 * kk + 1][0], a3 = pkA[2 * kk + 1][1];
            #pragma unroll
            for (int j = 0; j < 16; j++) {
                uint32_t b4[4];
                ldsm_x4(b4, vcur + j * 16 * VSTR + kk * 16);
                mma_bf16(oacc[2 * j],     a0, a1, a2, a3, b4[0], b4[1]);
                mma_bf16(oacc[2 * j + 1], a0, a1, a2, a3, b4[2], b4[3]);
            }
        }
        #pragma unroll
        for (int ni = 0; ni < 8; ni++) {
            pkA[ni][0] = pkB[ni][0];
            pkA[ni][1] = pkB[ni][1];
        }

        cpa_wait<0>();
        __syncthreads();
    }

    // ---- epilogue PV(63) ----
    {
        const bf16* vcur = vb[(FA_IT - 1) & 1];
        #pragma unroll
        for (int kk = 0; kk < 4; kk++) {
            uint32_t a0 = pkA[2 * kk][0], a1 = pkA[2 * kk][1];
            uint32_t a2 = pkA[2 * kk + 1][0], a3 = pkA[2 * kk + 1][1];
            #pragma unroll
            for (int j = 0; j < 16; j++) {
                uint32_t b4[4];
                ldsm_x4(b4, vcur + j * 16 * VSTR + kk * 16);
                mma_bf16(oacc[2 * j],     a0, a1, a2, a3, b4[0], b4[1]);
                mma_bf16(oacc[2 * j + 1], a0, a1, a2, a3, b4[2], b4[3]);
            }
        }
    }

    // ---- epilogue: reduce l across the quad, O /= l, store ----
    l0 += __shfl_xor_sync(0xffffffffu, l0, 1);
    l0 += __shfl_xor_sync(0xffffffffu, l0, 2);
    l1 += __shfl_xor_sync(0xffffffffu, l1, 1);
    l1 += __shfl_xor_sync(0xffffffffu, l1, 2);
    float i0 = 1.f / l0, i1 = 1.f / l1;
    bf16* orow = Og + ((size_t)b * NTOK + (size_t)qblk * FA_BM + r0) * FA_D;
    #pragma unroll
    for (int ni = 0; ni < 32; ni++) {
        int c = ni * 8 + tig * 2;
        *(__nv_bfloat162*)(orow + c) =
            __floats2bfloat162_rn(oacc[ni][0] * i0, oacc[ni][1] * i0);
        *(__nv_bfloat162*)(orow + (size_t)8 * FA_D + c) =
            __floats2bfloat162_rn(oacc[ni][2] * i1, oacc[ni][3] * i1);
    }
}

// ---------------- launcher ---------------------------------------------------
extern "C" void kernel_launch(void* const* d_in, const int* in_sizes, int n_in,
                              void* d_out, int out_size) {
    const float* x   = (const float*)d_in[0];
    const float* gns = (const float*)d_in[1];
    const float* gnb = (const float*)d_in[2];
    const float* wq  = (const float*)d_in[3];
    const float* bq  = (const float*)d_in[4];
    const float* wk  = (const float*)d_in[5];
    const float* bk  = (const float*)d_in[6];
    const float* wv  = (const float*)d_in[7];
    const float* bv  = (const float*)d_in[8];
    const float* wp  = (const float*)d_in[9];
    const float* bp  = (const float*)d_in[10];
    float* out = (float*)d_out;

    bf16 *p_h, *p_q, *p_k, *p_vT, *p_att, *p_w;
    cudaGetSymbolAddress((void**)&p_h,   g_h);
    cudaGetSymbolAddress((void**)&p_q,   g_q);
    cudaGetSymbolAddress((void**)&p_k,   g_k);
    cudaGetSymbolAddress((void**)&p_vT,  g_vT);
    cudaGetSymbolAddress((void**)&p_att, g_att);
    cudaGetSymbolAddress((void**)&p_w,   g_w);

    const size_t sNC = (size_t)NTOK * CH;
    const size_t sCN = (size_t)CH * NTOK;

    cudaFuncSetAttribute(fa_kernel, cudaFuncAttributeMaxDynamicSharedMemorySize, FA_SMEM);

    // 1) GroupNorm
    gn_stats<<<BATCH * NG, 256>>>(x);
    gn_apply<<<dim3(NTOK / 32, CH / 32, BATCH), dim3(32, 8)>>>(x, gns, gnb);
    conv_w<<<(CH * CH + 255) / 256, 256>>>(wq, wk, wv, wp);

    // 2) Q, K (row-major [N,C]) and V (col-major -> [C,N])
    dim3 gproj(CH / TBN, NTOK / TBM, BATCH);
    gemm_tn<<<gproj, 256>>>(p_h, p_w,               p_q,  nullptr, bq, nullptr,
                            1.f, NTOK, CH, CH, sNC, 0, sNC, 0, CH,   MODE_ROW);
    gemm_tn<<<gproj, 256>>>(p_h, p_w + CH * CH,     p_k,  nullptr, bk, nullptr,
                            1.f, NTOK, CH, CH, sNC, 0, sNC, 0, CH,   MODE_ROW);
    gemm_tn<<<gproj, 256>>>(p_h, p_w + 2 * CH * CH, p_vT, nullptr, bv, nullptr,
                            1.f, NTOK, CH, CH, sNC, 0, sCN, 0, NTOK, MODE_COL);

    // 3) fused attention: softmax(QK^T * C^-0.5) @ V  -> g_att [b][n][c]
    fa_kernel<<<dim3(NTOK / FA_BM, BATCH), 256, FA_SMEM>>>(p_q, p_k, p_vT, p_att);

    // 4) out = x + hatt @ wp^T + bp   (store transposed into [b][c][n] fp32)
    gemm_tn<<<dim3(CH / TBN, NTOK / TBM, BATCH), 256>>>(
        p_att, p_w + 3 * CH * CH, nullptr, out, bp, x,
        1.f, NTOK, CH, CH, sNC, 0, sCN, sCN, NTOK, MODE_RES);
}

// round 14
// speedup vs baseline: 1.1310x; 1.0703x over previous
#include <cuda_runtime.h>
#include <cuda_bf16.h>
#include <cstdint>
#include <cstddef>

typedef __nv_bfloat16 bf16;

#define BATCH 8
#define CH    256
#define NTOK  4096
#define NG    32
#define CPG   8
#define GEPS  1e-5f

// ---------------- scratch (__device__ globals: allocation-free rule) --------
__device__ bf16  g_h  [(size_t)BATCH * NTOK * CH];   // GN output, [b][n][c]
__device__ bf16  g_q  [(size_t)BATCH * NTOK * CH];   // [b][n][c]
__device__ bf16  g_k  [(size_t)BATCH * NTOK * CH];   // [b][n][c]
__device__ bf16  g_vT [(size_t)BATCH * CH * NTOK];   // [b][c][n]
__device__ bf16  g_att[(size_t)BATCH * NTOK * CH];   // attention output [b][n][c]
__device__ bf16  g_w  [4 * CH * CH];                 // wq, wk, wv, wp as bf16
__device__ float g_mean[BATCH * NG];
__device__ float g_rstd[BATCH * NG];

// ---------------- cp.async / ldmatrix / mma helpers -------------------------
__device__ __forceinline__ void cpa16(void* smem, const void* gmem) {
    uint32_t s = (uint32_t)__cvta_generic_to_shared(smem);
    asm volatile("cp.async.cg.shared.global [%0], [%1], 16;\n" :: "r"(s), "l"(gmem));
}
__device__ __forceinline__ void cpa_commit() {
    asm volatile("cp.async.commit_group;\n");
}
template<int N> __device__ __forceinline__ void cpa_wait() {
    asm volatile("cp.async.wait_group %0;\n" :: "n"(N));
}

__device__ __forceinline__ void ldsm_x4(uint32_t* r, const void* p) {
    uint32_t a = (uint32_t)__cvta_generic_to_shared(p);
    asm volatile("ldmatrix.sync.aligned.m8n8.x4.shared.b16 {%0,%1,%2,%3}, [%4];\n"
        : "=r"(r[0]), "=r"(r[1]), "=r"(r[2]), "=r"(r[3]) : "r"(a));
}

__device__ __forceinline__ void mma_bf16(float* c, const uint32_t a0, const uint32_t a1,
                                         const uint32_t a2, const uint32_t a3,
                                         const uint32_t b0, const uint32_t b1) {
    asm volatile(
        "mma.sync.aligned.m16n8k16.row.col.f32.bf16.bf16.f32 "
        "{%0,%1,%2,%3}, {%4,%5,%6,%7}, {%8,%9}, {%0,%1,%2,%3};\n"
        : "+f"(c[0]), "+f"(c[1]), "+f"(c[2]), "+f"(c[3])
        : "r"(a0), "r"(a1), "r"(a2), "r"(a3), "r"(b0), "r"(b1));
}

// ---------------- GroupNorm stats -------------------------------------------
__global__ void gn_stats(const float* __restrict__ x) {
    int b = blockIdx.x / NG, gid = blockIdx.x % NG;
    const float* base = x + ((size_t)b * CH + gid * CPG) * NTOK;
    const int total = CPG * NTOK;            // 32768
    const float4* p = (const float4*)base;
    float s = 0.f, ss = 0.f;
    for (int i = threadIdx.x; i < total / 4; i += blockDim.x) {
        float4 v = p[i];
        s  += v.x + v.y + v.z + v.w;
        ss += v.x * v.x + v.y * v.y + v.z * v.z + v.w * v.w;
    }
    __shared__ float shm[64];
    #pragma unroll
    for (int o = 16; o; o >>= 1) {
        s  += __shfl_xor_sync(0xffffffffu, s, o);
        ss += __shfl_xor_sync(0xffffffffu, ss, o);
    }
    int w = threadIdx.x >> 5;
    if ((threadIdx.x & 31) == 0) { shm[w] = s; shm[32 + w] = ss; }
    __syncthreads();
    if (threadIdx.x < 32) {
        int nw = blockDim.x >> 5;
        s  = threadIdx.x < nw ? shm[threadIdx.x] : 0.f;
        ss = threadIdx.x < nw ? shm[32 + threadIdx.x] : 0.f;
        #pragma unroll
        for (int o = 16; o; o >>= 1) {
            s  += __shfl_xor_sync(0xffffffffu, s, o);
            ss += __shfl_xor_sync(0xffffffffu, ss, o);
        }
        if (threadIdx.x == 0) {
            float m   = s / (float)total;
            float var = ss / (float)total - m * m;
            g_mean[blockIdx.x] = m;
            g_rstd[blockIdx.x] = rsqrtf(var + GEPS);
        }
    }
}

// ---------------- GroupNorm apply + transpose to [b][n][c] bf16 -------------
__global__ void gn_apply(const float* __restrict__ x,
                         const float* __restrict__ sc,
                         const float* __restrict__ bi) {
    __shared__ float tile[32][33];
    int b  = blockIdx.z;
    int c0 = blockIdx.y * 32, n0 = blockIdx.x * 32;
    int tx = threadIdx.x, ty = threadIdx.y;   // 32 x 8
    #pragma unroll
    for (int j = 0; j < 4; j++) {
        int c = c0 + ty + j * 8;
        float m = g_mean[b * NG + (c >> 3)];
        float r = g_rstd[b * NG + (c >> 3)];
        float v = x[((size_t)b * CH + c) * NTOK + n0 + tx];
        tile[ty + j * 8][tx] = (v - m) * r * sc[c] + bi[c];
    }
    __syncthreads();
    #pragma unroll
    for (int j = 0; j < 4; j++) {
        int n = n0 + ty + j * 8;
        int c = c0 + tx;
        g_h[((size_t)b * NTOK + n) * CH + c] = __float2bfloat16(tile[tx][ty + j * 8]);
    }
}

// ---------------- weight conversion fp32 -> bf16 ----------------------------
__global__ void conv_w(const float* __restrict__ wq, const float* __restrict__ wk,
                       const float* __restrict__ wv, const float* __restrict__ wp) {
    int i = blockIdx.x * blockDim.x + threadIdx.x;
    if (i < CH * CH) {
        g_w[i]               = __float2bfloat16(wq[i]);
        g_w[CH * CH + i]     = __float2bfloat16(wk[i]);
        g_w[2 * CH * CH + i] = __float2bfloat16(wv[i]);
        g_w[3 * CH * CH + i] = __float2bfloat16(wp[i]);
    }
}

// ---------------- generic TN GEMM (TBK=32, double-buffered, ldmatrix) -------
#define TBM 128
#define TBN 128
#define TBK 32
#define SPAD 8
#define GSTR (TBK + SPAD)

#define MODE_ROW 0
#define MODE_COL 1
#define MODE_RES 2

__global__ __launch_bounds__(256, 2) void gemm_tn(
    const bf16* __restrict__ A, const bf16* __restrict__ Bm,
    bf16* outb, float* outf,
    const float* __restrict__ bias, const float* __restrict__ resid,
    float alpha, int M, int N, int K,
    size_t strideA, size_t strideB, size_t strideO, size_t strideX,
    int ldo, int mode)
{
    __shared__ bf16 sA[2][TBM][GSTR];
    __shared__ bf16 sB[2][TBN][GSTR];

    int b = blockIdx.z;
    const bf16* Ab = A + (size_t)b * strideA + (size_t)blockIdx.y * TBM * K;
    const bf16* Bb = Bm + (size_t)b * strideB + (size_t)blockIdx.x * TBN * K;

    int tid  = threadIdx.x;
    int lane = tid & 31, warp = tid >> 5;
    int wm = warp >> 2, wn = warp & 3;
    int g  = lane >> 2, tig = lane & 3;
    int lm = lane >> 3, li = lane & 7;

    int lrow = tid >> 2;
    int lc8  = (tid & 3) << 3;

    float acc[4][4][4];
    #pragma unroll
    for (int i = 0; i < 4; i++)
        #pragma unroll
        for (int j = 0; j < 4; j++)
            #pragma unroll
            for (int q = 0; q < 4; q++) acc[i][j][q] = 0.f;

    #pragma unroll
    for (int r = 0; r < 2; r++) {
        int row = lrow + r * 64;
        cpa16(&sA[0][row][lc8], Ab + (size_t)row * K + lc8);
        cpa16(&sB[0][row][lc8], Bb + (size_t)row * K + lc8);
    }
    cpa_commit();

    int nk = K / TBK;
    for (int t = 0; t < nk; t++) {
        int buf = t & 1;
        if (t + 1 < nk) {
            int kt = (t + 1) * TBK;
            #pragma unroll
            for (int r = 0; r < 2; r++) {
                int row = lrow + r * 64;
                cpa16(&sA[buf ^ 1][row][lc8], Ab + (size_t)row * K + kt + lc8);
                cpa16(&sB[buf ^ 1][row][lc8], Bb + (size_t)row * K + kt + lc8);
            }
            cpa_commit();
            cpa_wait<1>();
        } else {
            cpa_wait<0>();
        }
        __syncthreads();

        #pragma unroll
        for (int kk = 0; kk < 2; kk++) {
            uint32_t af[4][4];
            #pragma unroll
            for (int mi = 0; mi < 4; mi++)
                ldsm_x4(af[mi],
                        &sA[buf][wm * 64 + mi * 16 + (lm & 1) * 8 + li]
                               [kk * 16 + (lm >> 1) * 8]);
            uint32_t bfr[2][4];
            #pragma unroll
            for (int j = 0; j < 2; j++)
                ldsm_x4(bfr[j],
                        &sB[buf][wn * 32 + j * 16 + (lm >> 1) * 8 + li]
                               [kk * 16 + (lm & 1) * 8]);
            #pragma unroll
            for (int mi = 0; mi < 4; mi++)
                #pragma unroll
                for (int ni = 0; ni < 4; ni++)
                    mma_bf16(acc[mi][ni], af[mi][0], af[mi][1], af[mi][2], af[mi][3],
                             bfr[ni >> 1][(ni & 1) * 2], bfr[ni >> 1][(ni & 1) * 2 + 1]);
        }
        __syncthreads();
    }

    #pragma unroll
    for (int mi = 0; mi < 4; mi++) {
        #pragma unroll
        for (int ni = 0; ni < 4; ni++) {
            int row = blockIdx.y * TBM + wm * 64 + mi * 16 + g;
            int col = blockIdx.x * TBN + wn * 32 + ni * 8 + tig * 2;
            float v0 = acc[mi][ni][0] * alpha;
            float v1 = acc[mi][ni][1] * alpha;
            float v2 = acc[mi][ni][2] * alpha;
            float v3 = acc[mi][ni][3] * alpha;
            if (bias) {
                float b0 = bias[col], b1 = bias[col + 1];
                v0 += b0; v1 += b1; v2 += b0; v3 += b1;
            }
            if (mode == MODE_ROW) {
                bf16* o = outb + (size_t)b * strideO + (size_t)row * ldo + col;
                *(__nv_bfloat162*)o = __floats2bfloat162_rn(v0, v1);
                *(__nv_bfloat162*)(o + (size_t)8 * ldo) = __floats2bfloat162_rn(v2, v3);
            } else if (mode == MODE_COL) {
                bf16* o = outb + (size_t)b * strideO;
                o[(size_t)col * ldo + row]           = __float2bfloat16(v0);
                o[(size_t)(col + 1) * ldo + row]     = __float2bfloat16(v1);
                o[(size_t)col * ldo + row + 8]       = __float2bfloat16(v2);
                o[(size_t)(col + 1) * ldo + row + 8] = __float2bfloat16(v3);
            } else {
                float* o = outf + (size_t)b * strideO;
                const float* xr = resid + (size_t)b * strideX;
                size_t i00 = (size_t)col * ldo + row;
                size_t i10 = (size_t)(col + 1) * ldo + row;
                o[i00]     = xr[i00]     + v0;
                o[i10]     = xr[i10]     + v1;
                o[i00 + 8] = xr[i00 + 8] + v2;
                o[i10 + 8] = xr[i10 + 8] + v3;
            }
        }
    }
}

// ---------------- fused flash attention (fixed-shift softmax + ldmatrix, ----
// exp software-pipelined into the PV MMA stream). R10 tile shape: BM=BN=128.
#define FA_BM 128
#define FA_BN 128
#define FA_D  256
#define FA_IT (NTOK / FA_BN)      // 32
#define QSTR  (FA_D + 8)          // 264 elems = 528 B
#define VSTR  (FA_BN + 8)         // 136 elems = 272 B
#define FA_C1 0.09016844f         // (1/16) * log2(e)
#define FA_C2 -17.3123404906676f  // -12 * log2(e)

__device__ __forceinline__ void fa_load_qk(bf16* s, const bf16* gsrc, int tid) {
    #pragma unroll
    for (int t = 0; t < 16; t++) {
        int idx = t * 256 + tid;       // 0..4095
        int r = idx >> 5;              // 0..127
        int c = (idx & 31) << 3;       // 0..248
        cpa16(s + r * QSTR + c, gsrc + (size_t)r * FA_D + c);
    }
}
__device__ __forceinline__ void fa_load_v(bf16* s, const bf16* gsrc, int tid) {
    #pragma unroll
    for (int t = 0; t < 16; t++) {
        int idx = t * 256 + tid;       // 0..4095
        int r = idx >> 4;              // 0..255
        int c = (idx & 15) << 3;       // 0..120
        cpa16(s + r * VSTR + c, gsrc + (size_t)r * NTOK + c);
    }
}

// exp one S fragment -> one packed P fragment (+ row-sum accumulation)
__device__ __forceinline__ void fa_expfrag(const float* s, uint32_t* p,
                                           float& l0, float& l1) {
    float e0 = exp2f(fmaf(s[0], FA_C1, FA_C2));
    float e1 = exp2f(fmaf(s[1], FA_C1, FA_C2));
    float e2 = exp2f(fmaf(s[2], FA_C1, FA_C2));
    float e3 = exp2f(fmaf(s[3], FA_C1, FA_C2));
    l0 += e0 + e1; l1 += e2 + e3;
    __nv_bfloat162 t01 = __floats2bfloat162_rn(e0, e1);
    __nv_bfloat162 t23 = __floats2bfloat162_rn(e2, e3);
    p[0] = *(uint32_t*)&t01;
    p[1] = *(uint32_t*)&t23;
}

__global__ __launch_bounds__(256) void fa_kernel(
    const bf16* __restrict__ Qg,    // [b][n][c]
    const bf16* __restrict__ Kg,    // [b][n][c]
    const bf16* __restrict__ Vt,    // [b][c][n]
    bf16* __restrict__ Og)          // [b][n][c]
{
    extern __shared__ bf16 fsm[];
    bf16* sQ = fsm;                       // [128][QSTR]
    bf16* sK = sQ + FA_BM * QSTR;         // [128][QSTR]
    bf16* sV = sK + FA_BM * QSTR;         // [256][VSTR]

    const int b = blockIdx.y;
    const int qblk = blockIdx.x;

    const bf16* Qb = Qg + ((size_t)b * NTOK + (size_t)qblk * FA_BM) * FA_D;
    const bf16* Kb = Kg + (size_t)b * NTOK * FA_D;
    const bf16* Vb = Vt + (size_t)b * FA_D * NTOK;

    const int tid = threadIdx.x;
    const int lane = tid & 31, w = tid >> 5;
    const int g = lane >> 2, tig = lane & 3;
    const int lm = lane >> 3, li = lane & 7;
    const int r0 = w * 16 + g;            // local Q row (and r0+8)

    // per-lane ldmatrix row bases
    const bf16* qbase = sQ + (w * 16 + (lm & 1) * 8 + li) * QSTR + (lm >> 1) * 8;
    const bf16* kbase = sK + ((lm >> 1) * 8 + li) * QSTR + (lm & 1) * 8;
    const bf16* vbase = sV + ((lm >> 1) * 8 + li) * VSTR + (lm & 1) * 8;

    // prologue: group1 = Q + K0, group2 = V0
    fa_load_qk(sQ, Qb, tid);
    fa_load_qk(sK, Kb, tid);
    cpa_commit();
    fa_load_v(sV, Vb, tid);
    cpa_commit();

    float oacc[32][4];
    #pragma unroll
    for (int i = 0; i < 32; i++)
        #pragma unroll
        for (int q = 0; q < 4; q++) oacc[i][q] = 0.f;
    float l0 = 0.f, l1 = 0.f;   // per-thread partial row sums

    for (int it = 0; it < FA_IT; it++) {
        // ---- wait Q/K_it (V_it may still be in flight) ----
        cpa_wait<1>();
        __syncthreads();

        // ---- S = Q K^T over D=256 ----
        float sacc[16][4];
        #pragma unroll
        for (int i = 0; i < 16; i++)
            #pragma unroll
            for (int q = 0; q < 4; q++) sacc[i][q] = 0.f;

        #pragma unroll
        for (int ks = 0; ks < 16; ks++) {
            uint32_t a[4];
            ldsm_x4(a, qbase + ks * 16);
            #pragma unroll
            for (int j = 0; j < 8; j++) {
                uint32_t bf4[4];
                ldsm_x4(bf4, kbase + j * 16 * QSTR + ks * 16);
                mma_bf16(sacc[2 * j],     a[0], a[1], a[2], a[3], bf4[0], bf4[1]);
                mma_bf16(sacc[2 * j + 1], a[0], a[1], a[2], a[3], bf4[2], bf4[3]);
            }
        }
        __syncthreads();   // all warps done reading sK

        // ---- prefetch K_{it+1} ----
        if (it + 1 < FA_IT) {
            fa_load_qk(sK, Kb + (size_t)(it + 1) * FA_BN * FA_D, tid);
            cpa_commit();
        }

        // ---- exp for first PV chunk (hides under the V wait) ----
        uint32_t pk[16][2];
        fa_expfrag(sacc[0], pk[0], l0, l1);
        fa_expfrag(sacc[1], pk[1], l0, l1);

        // ---- wait V_it ----
        if (it + 1 < FA_IT) cpa_wait<1>(); else cpa_wait<0>();
        __syncthreads();

        // ---- O += P @ V, exp(next chunk) interleaved with MMA(this chunk) --
        #pragma unroll
        for (int kk = 0; kk < 8; kk++) {
            uint32_t a0 = pk[2 * kk][0];
            uint32_t a1 = pk[2 * kk][1];
            uint32_t a2 = pk[2 * kk + 1][0];
            uint32_t a3 = pk[2 * kk + 1][1];
            if (kk < 7) {
                fa_expfrag(sacc[2 * kk + 2], pk[2 * kk + 2], l0, l1);
                fa_expfrag(sacc[2 * kk + 3], pk[2 * kk + 3], l0, l1);
            }
            #pragma unroll
            for (int j = 0; j < 16; j++) {
                uint32_t bf4[4];
                ldsm_x4(bf4, vbase + j * 16 * VSTR + kk * 16);
                mma_bf16(oacc[2 * j],     a0, a1, a2, a3, bf4[0], bf4[1]);
                mma_bf16(oacc[2 * j + 1], a0, a1, a2, a3, bf4[2], bf4[3]);
            }
        }
        __syncthreads();   // all warps done reading sV

        // ---- prefetch V_{it+1} ----
        if (it + 1 < FA_IT) {
            fa_load_v(sV, Vb + (size_t)(it + 1) * FA_BN, tid);
            cpa_commit();
        }
    }

    // ---- epilogue: reduce l across the quad (tig lanes), O /= l, store ----
    l0 += __shfl_xor_sync(0xffffffffu, l0, 1);
    l0 += __shfl_xor_sync(0xffffffffu, l0, 2);
    l1 += __shfl_xor_sync(0xffffffffu, l1, 1);
    l1 += __shfl_xor_sync(0xffffffffu, l1, 2);
    float i0 = 1.f / l0, i1 = 1.f / l1;
    bf16* orow = Og + ((size_t)b * NTOK + (size_t)qblk * FA_BM + r0) * FA_D;
    #pragma unroll
    for (int ni = 0; ni < 32; ni++) {
        int c = ni * 8 + tig * 2;
        *(__nv_bfloat162*)(orow + c) =
            __floats2bfloat162_rn(oacc[ni][0] * i0, oacc[ni][1] * i0);
        *(__nv_bfloat162*)(orow + (size_t)8 * FA_D + c) =
            __floats2bfloat162_rn(oacc[ni][2] * i1, oacc[ni][3] * i1);
    }
}

// ---------------- launcher ---------------------------------------------------
extern "C" void kernel_launch(void* const* d_in, const int* in_sizes, int n_in,
                              void* d_out, int out_size) {
    const float* x   = (const float*)d_in[0];
    const float* gns = (const float*)d_in[1];
    const float* gnb = (const float*)d_in[2];
    const float* wq  = (const float*)d_in[3];
    const float* bq  = (const float*)d_in[4];
    const float* wk  = (const float*)d_in[5];
    const float* bk  = (const float*)d_in[6];
    const float* wv  = (const float*)d_in[7];
    const float* bv  = (const float*)d_in[8];
    const float* wp  = (const float*)d_in[9];
    const float* bp  = (const float*)d_in[10];
    float* out = (float*)d_out;

    bf16 *p_h, *p_q, *p_k, *p_vT, *p_att, *p_w;
    cudaGetSymbolAddress((void**)&p_h,   g_h);
    cudaGetSymbolAddress((void**)&p_q,   g_q);
    cudaGetSymbolAddress((void**)&p_k,   g_k);
    cudaGetSymbolAddress((void**)&p_vT,  g_vT);
    cudaGetSymbolAddress((void**)&p_att, g_att);
    cudaGetSymbolAddress((void**)&p_w,   g_w);

    const size_t sNC = (size_t)NTOK * CH;
    const size_t sCN = (size_t)CH * NTOK;

    const int fa_smem = (FA_BM * QSTR + FA_BM * QSTR + FA_D * VSTR) * (int)sizeof(bf16);
    cudaFuncSetAttribute(fa_kernel, cudaFuncAttributeMaxDynamicSharedMemorySize, fa_smem);

    // 1) GroupNorm
    gn_stats<<<BATCH * NG, 256>>>(x);
    gn_apply<<<dim3(NTOK / 32, CH / 32, BATCH), dim3(32, 8)>>>(x, gns, gnb);
    conv_w<<<(CH * CH + 255) / 256, 256>>>(wq, wk, wv, wp);

    // 2) Q, K (row-major [N,C]) and V (col-major -> [C,N])
    dim3 gproj(CH / TBN, NTOK / TBM, BATCH);
    gemm_tn<<<gproj, 256>>>(p_h, p_w,               p_q,  nullptr, bq, nullptr,
                            1.f, NTOK, CH, CH, sNC, 0, sNC, 0, CH,   MODE_ROW);
    gemm_tn<<<gproj, 256>>>(p_h, p_w + CH * CH,     p_k,  nullptr, bk, nullptr,
                            1.f, NTOK, CH, CH, sNC, 0, sNC, 0, CH,   MODE_ROW);
    gemm_tn<<<gproj, 256>>>(p_h, p_w + 2 * CH * CH, p_vT, nullptr, bv, nullptr,
                            1.f, NTOK, CH, CH, sNC, 0, sCN, 0, NTOK, MODE_COL);

    // 3) fused attention: softmax(QK^T * C^-0.5) @ V  -> g_att [b][n][c]
    fa_kernel<<<dim3(NTOK / FA_BM, BATCH), 256, fa_smem>>>(p_q, p_k, p_vT, p_att);

    // 4) out = x + hatt @ wp^T + bp   (store transposed into [b][c][n] fp32)
    gemm_tn<<<dim3(CH / TBN, NTOK / TBM, BATCH), 256>>>(
        p_att, p_w + 3 * CH * CH, nullptr, out, bp, x,
        1.f, NTOK, CH, CH, sNC, 0, sCN, sCN, NTOK, MODE_RES);
}

// round 15
// speedup vs baseline: 1.1470x; 1.0141x over previous
#include <cuda_runtime.h>
#include <cuda_bf16.h>
#include <cstdint>
#include <cstddef>

typedef __nv_bfloat16 bf16;

#define BATCH 8
#define CH    256
#define NTOK  4096
#define NG    32
#define CPG   8
#define GEPS  1e-5f

// ---------------- scratch (__device__ globals: allocation-free rule) --------
__device__ bf16  g_h  [(size_t)BATCH * NTOK * CH];   // GN output, [b][n][c]
__device__ bf16  g_q  [(size_t)BATCH * NTOK * CH];   // [b][n][c]
__device__ bf16  g_k  [(size_t)BATCH * NTOK * CH];   // [b][n][c]
__device__ bf16  g_vT [(size_t)BATCH * CH * NTOK];   // [b][c][n]
__device__ bf16  g_att[(size_t)BATCH * NTOK * CH];   // attention output [b][n][c]
__device__ bf16  g_w  [4 * CH * CH];                 // wq, wk, wv, wp as bf16
__device__ float g_mean[BATCH * NG];
__device__ float g_rstd[BATCH * NG];

// ---------------- cp.async / ldmatrix / mma helpers -------------------------
__device__ __forceinline__ void cpa16(void* smem, const void* gmem) {
    uint32_t s = (uint32_t)__cvta_generic_to_shared(smem);
    asm volatile("cp.async.cg.shared.global [%0], [%1], 16;\n" :: "r"(s), "l"(gmem));
}
__device__ __forceinline__ void cpa_commit() {
    asm volatile("cp.async.commit_group;\n");
}
template<int N> __device__ __forceinline__ void cpa_wait() {
    asm volatile("cp.async.wait_group %0;\n" :: "n"(N));
}

__device__ __forceinline__ void ldsm_x4(uint32_t* r, const void* p) {
    uint32_t a = (uint32_t)__cvta_generic_to_shared(p);
    asm volatile("ldmatrix.sync.aligned.m8n8.x4.shared.b16 {%0,%1,%2,%3}, [%4];\n"
        : "=r"(r[0]), "=r"(r[1]), "=r"(r[2]), "=r"(r[3]) : "r"(a));
}

__device__ __forceinline__ void mma_bf16(float* c, const uint32_t a0, const uint32_t a1,
                                         const uint32_t a2, const uint32_t a3,
                                         const uint32_t b0, const uint32_t b1) {
    asm volatile(
        "mma.sync.aligned.m16n8k16.row.col.f32.bf16.bf16.f32 "
        "{%0,%1,%2,%3}, {%4,%5,%6,%7}, {%8,%9}, {%0,%1,%2,%3};\n"
        : "+f"(c[0]), "+f"(c[1]), "+f"(c[2]), "+f"(c[3])
        : "r"(a0), "r"(a1), "r"(a2), "r"(a3), "r"(b0), "r"(b1));
}

// ---------------- GroupNorm stats -------------------------------------------
__global__ void gn_stats(const float* __restrict__ x) {
    int b = blockIdx.x / NG, gid = blockIdx.x % NG;
    const float* base = x + ((size_t)b * CH + gid * CPG) * NTOK;
    const int total = CPG * NTOK;            // 32768
    const float4* p = (const float4*)base;
    float s = 0.f, ss = 0.f;
    for (int i = threadIdx.x; i < total / 4; i += blockDim.x) {
        float4 v = p[i];
        s  += v.x + v.y + v.z + v.w;
        ss += v.x * v.x + v.y * v.y + v.z * v.z + v.w * v.w;
    }
    __shared__ float shm[64];
    #pragma unroll
    for (int o = 16; o; o >>= 1) {
        s  += __shfl_xor_sync(0xffffffffu, s, o);
        ss += __shfl_xor_sync(0xffffffffu, ss, o);
    }
    int w = threadIdx.x >> 5;
    if ((threadIdx.x & 31) == 0) { shm[w] = s; shm[32 + w] = ss; }
    __syncthreads();
    if (threadIdx.x < 32) {
        int nw = blockDim.x >> 5;
        s  = threadIdx.x < nw ? shm[threadIdx.x] : 0.f;
        ss = threadIdx.x < nw ? shm[32 + threadIdx.x] : 0.f;
        #pragma unroll
        for (int o = 16; o; o >>= 1) {
            s  += __shfl_xor_sync(0xffffffffu, s, o);
            ss += __shfl_xor_sync(0xffffffffu, ss, o);
        }
        if (threadIdx.x == 0) {
            float m   = s / (float)total;
            float var = ss / (float)total - m * m;
            g_mean[blockIdx.x] = m;
            g_rstd[blockIdx.x] = rsqrtf(var + GEPS);
        }
    }
}

// ---------------- GroupNorm apply + transpose to [b][n][c] bf16 -------------
__global__ void gn_apply(const float* __restrict__ x,
                         const float* __restrict__ sc,
                         const float* __restrict__ bi) {
    __shared__ float tile[32][33];
    int b  = blockIdx.z;
    int c0 = blockIdx.y * 32, n0 = blockIdx.x * 32;
    int tx = threadIdx.x, ty = threadIdx.y;   // 32 x 8
    #pragma unroll
    for (int j = 0; j < 4; j++) {
        int c = c0 + ty + j * 8;
        float m = g_mean[b * NG + (c >> 3)];
        float r = g_rstd[b * NG + (c >> 3)];
        float v = x[((size_t)b * CH + c) * NTOK + n0 + tx];
        tile[ty + j * 8][tx] = (v - m) * r * sc[c] + bi[c];
    }
    __syncthreads();
    #pragma unroll
    for (int j = 0; j < 4; j++) {
        int n = n0 + ty + j * 8;
        int c = c0 + tx;
        g_h[((size_t)b * NTOK + n) * CH + c] = __float2bfloat16(tile[tx][ty + j * 8]);
    }
}

// ---------------- weight conversion fp32 -> bf16 ----------------------------
__global__ void conv_w(const float* __restrict__ wq, const float* __restrict__ wk,
                       const float* __restrict__ wv, const float* __restrict__ wp) {
    int i = blockIdx.x * blockDim.x + threadIdx.x;
    if (i < CH * CH) {
        g_w[i]               = __float2bfloat16(wq[i]);
        g_w[CH * CH + i]     = __float2bfloat16(wk[i]);
        g_w[2 * CH * CH + i] = __float2bfloat16(wv[i]);
        g_w[3 * CH * CH + i] = __float2bfloat16(wp[i]);
    }
}

// ---------------- generic TN GEMM (TBK=64, double-buffered, ldmatrix, -------
// dynamic smem, occupancy forced to 2 CTAs/SM so regs cap at 128) ------------
#define TBM 128
#define TBN 128
#define TBK 64
#define SPAD 8
#define GSTR (TBK + SPAD)    // 72 elems = 144 B row stride (16B-divisible)
#define GEMM_SMEM (2 * (TBM + TBN) * GSTR * (int)sizeof(bf16))   // 73728 B

#define MODE_ROW 0
#define MODE_COL 1
#define MODE_RES 2

__global__ __launch_bounds__(256, 2) void gemm_tn(
    const bf16* __restrict__ A, const bf16* __restrict__ Bm,
    bf16* outb, float* outf,
    const float* __restrict__ bias, const float* __restrict__ resid,
    float alpha, int M, int N, int K,
    size_t strideA, size_t strideB, size_t strideO, size_t strideX,
    int ldo, int mode)
{
    extern __shared__ bf16 gsm[];
    bf16* sAb[2] = { gsm,                  gsm + TBM * GSTR };
    bf16* sBb[2] = { gsm + 2 * TBM * GSTR, gsm + 2 * TBM * GSTR + TBN * GSTR };

    int b = blockIdx.z;
    const bf16* Ab = A + (size_t)b * strideA + (size_t)blockIdx.y * TBM * K;
    const bf16* Bb = Bm + (size_t)b * strideB + (size_t)blockIdx.x * TBN * K;

    int tid  = threadIdx.x;
    int lane = tid & 31, warp = tid >> 5;
    int wm = warp >> 2, wn = warp & 3;       // 2 x 4 warps, warp tile 64(M) x 32(N)
    int g  = lane >> 2, tig = lane & 3;
    int lm = lane >> 3, li = lane & 7;       // ldmatrix lane roles

    float acc[4][4][4];
    #pragma unroll
    for (int i = 0; i < 4; i++)
        #pragma unroll
        for (int j = 0; j < 4; j++)
            #pragma unroll
            for (int q = 0; q < 4; q++) acc[i][j][q] = 0.f;

    // each tile: 128 rows x 8 chunks(16B) = 1024 slots; thread does 4 per matrix
    #pragma unroll
    for (int r = 0; r < 4; r++) {
        int slot = tid + r * 256;
        int row = slot >> 3, c8 = (slot & 7) << 3;
        cpa16(sAb[0] + row * GSTR + c8, Ab + (size_t)row * K + c8);
        cpa16(sBb[0] + row * GSTR + c8, Bb + (size_t)row * K + c8);
    }
    cpa_commit();

    int nk = K / TBK;
    for (int t = 0; t < nk; t++) {
        int buf = t & 1;
        if (t + 1 < nk) {
            int kt = (t + 1) * TBK;
            #pragma unroll
            for (int r = 0; r < 4; r++) {
                int slot = tid + r * 256;
                int row = slot >> 3, c8 = (slot & 7) << 3;
                cpa16(sAb[buf ^ 1] + row * GSTR + c8, Ab + (size_t)row * K + kt + c8);
                cpa16(sBb[buf ^ 1] + row * GSTR + c8, Bb + (size_t)row * K + kt + c8);
            }
            cpa_commit();
            cpa_wait<1>();
        } else {
            cpa_wait<0>();
        }
        __syncthreads();

        const bf16* sA = sAb[buf];
        const bf16* sB = sBb[buf];
        #pragma unroll
        for (int kk = 0; kk < 4; kk++) {
            uint32_t af[4][4];
            #pragma unroll
            for (int mi = 0; mi < 4; mi++)
                ldsm_x4(af[mi],
                        sA + (wm * 64 + mi * 16 + (lm & 1) * 8 + li) * GSTR
                           + kk * 16 + (lm >> 1) * 8);
            uint32_t bfr[2][4];
            #pragma unroll
            for (int j = 0; j < 2; j++)
                ldsm_x4(bfr[j],
                        sB + (wn * 32 + j * 16 + (lm >> 1) * 8 + li) * GSTR
                           + kk * 16 + (lm & 1) * 8);
            #pragma unroll
            for (int mi = 0; mi < 4; mi++)
                #pragma unroll
                for (int ni = 0; ni < 4; ni++)
                    mma_bf16(acc[mi][ni], af[mi][0], af[mi][1], af[mi][2], af[mi][3],
                             bfr[ni >> 1][(ni & 1) * 2], bfr[ni >> 1][(ni & 1) * 2 + 1]);
        }
        __syncthreads();
    }

    // -------- epilogue --------
    #pragma unroll
    for (int mi = 0; mi < 4; mi++) {
        #pragma unroll
        for (int ni = 0; ni < 4; ni++) {
            int row = blockIdx.y * TBM + wm * 64 + mi * 16 + g;
            int col = blockIdx.x * TBN + wn * 32 + ni * 8 + tig * 2;
            float v0 = acc[mi][ni][0] * alpha;
            float v1 = acc[mi][ni][1] * alpha;
            float v2 = acc[mi][ni][2] * alpha;
            float v3 = acc[mi][ni][3] * alpha;
            if (bias) {
                float b0 = bias[col], b1 = bias[col + 1];
                v0 += b0; v1 += b1; v2 += b0; v3 += b1;
            }
            if (mode == MODE_ROW) {
                bf16* o = outb + (size_t)b * strideO + (size_t)row * ldo + col;
                *(__nv_bfloat162*)o = __floats2bfloat162_rn(v0, v1);
                *(__nv_bfloat162*)(o + (size_t)8 * ldo) = __floats2bfloat162_rn(v2, v3);
            } else if (mode == MODE_COL) {
                bf16* o = outb + (size_t)b * strideO;
                o[(size_t)col * ldo + row]           = __float2bfloat16(v0);
                o[(size_t)(col + 1) * ldo + row]     = __float2bfloat16(v1);
                o[(size_t)col * ldo + row + 8]       = __float2bfloat16(v2);
                o[(size_t)(col + 1) * ldo + row + 8] = __float2bfloat16(v3);
            } else {
                float* o = outf + (size_t)b * strideO;
                const float* xr = resid + (size_t)b * strideX;
                size_t i00 = (size_t)col * ldo + row;
                size_t i10 = (size_t)(col + 1) * ldo + row;
                o[i00]     = xr[i00]     + v0;
                o[i10]     = xr[i10]     + v1;
                o[i00 + 8] = xr[i00 + 8] + v2;
                o[i10 + 8] = xr[i10 + 8] + v3;
            }
        }
    }
}

// ---------------- fused flash attention (fixed-shift softmax + ldmatrix, ----
// exp software-pipelined into the PV MMA stream). R14-proven.
#define FA_BM 128
#define FA_BN 128
#define FA_D  256
#define FA_IT (NTOK / FA_BN)      // 32
#define QSTR  (FA_D + 8)          // 264 elems = 528 B
#define VSTR  (FA_BN + 8)         // 136 elems = 272 B
#define FA_C1 0.09016844f         // (1/16) * log2(e)
#define FA_C2 -17.3123404906676f  // -12 * log2(e)

__device__ __forceinline__ void fa_load_qk(bf16* s, const bf16* gsrc, int tid) {
    #pragma unroll
    for (int t = 0; t < 16; t++) {
        int idx = t * 256 + tid;       // 0..4095
        int r = idx >> 5;              // 0..127
        int c = (idx & 31) << 3;       // 0..248
        cpa16(s + r * QSTR + c, gsrc + (size_t)r * FA_D + c);
    }
}
__device__ __forceinline__ void fa_load_v(bf16* s, const bf16* gsrc, int tid) {
    #pragma unroll
    for (int t = 0; t < 16; t++) {
        int idx = t * 256 + tid;       // 0..4095
        int r = idx >> 4;              // 0..255
        int c = (idx & 15) << 3;       // 0..120
        cpa16(s + r * VSTR + c, gsrc + (size_t)r * NTOK + c);
    }
}

// exp one S fragment -> one packed P fragment (+ row-sum accumulation)
__device__ __forceinline__ void fa_expfrag(const float* s, uint32_t* p,
                                           float& l0, float& l1) {
    float e0 = exp2f(fmaf(s[0], FA_C1, FA_C2));
    float e1 = exp2f(fmaf(s[1], FA_C1, FA_C2));
    float e2 = exp2f(fmaf(s[2], FA_C1, FA_C2));
    float e3 = exp2f(fmaf(s[3], FA_C1, FA_C2));
    l0 += e0 + e1; l1 += e2 + e3;
    __nv_bfloat162 t01 = __floats2bfloat162_rn(e0, e1);
    __nv_bfloat162 t23 = __floats2bfloat162_rn(e2, e3);
    p[0] = *(uint32_t*)&t01;
    p[1] = *(uint32_t*)&t23;
}

__global__ __launch_bounds__(256) void fa_kernel(
    const bf16* __restrict__ Qg,    // [b][n][c]
    const bf16* __restrict__ Kg,    // [b][n][c]
    const bf16* __restrict__ Vt,    // [b][c][n]
    bf16* __restrict__ Og)          // [b][n][c]
{
    extern __shared__ bf16 fsm[];
    bf16* sQ = fsm;                       // [128][QSTR]
    bf16* sK = sQ + FA_BM * QSTR;         // [128][QSTR]
    bf16* sV = sK + FA_BM * QSTR;         // [256][VSTR]

    const int b = blockIdx.y;
    const int qblk = blockIdx.x;

    const bf16* Qb = Qg + ((size_t)b * NTOK + (size_t)qblk * FA_BM) * FA_D;
    const bf16* Kb = Kg + (size_t)b * NTOK * FA_D;
    const bf16* Vb = Vt + (size_t)b * FA_D * NTOK;

    const int tid = threadIdx.x;
    const int lane = tid & 31, w = tid >> 5;
    const int g = lane >> 2, tig = lane & 3;
    const int lm = lane >> 3, li = lane & 7;
    const int r0 = w * 16 + g;            // local Q row (and r0+8)

    // per-lane ldmatrix row bases
    const bf16* qbase = sQ + (w * 16 + (lm & 1) * 8 + li) * QSTR + (lm >> 1) * 8;
    const bf16* kbase = sK + ((lm >> 1) * 8 + li) * QSTR + (lm & 1) * 8;
    const bf16* vbase = sV + ((lm >> 1) * 8 + li) * VSTR + (lm & 1) * 8;

    // prologue: group1 = Q + K0, group2 = V0
    fa_load_qk(sQ, Qb, tid);
    fa_load_qk(sK, Kb, tid);
    cpa_commit();
    fa_load_v(sV, Vb, tid);
    cpa_commit();

    float oacc[32][4];
    #pragma unroll
    for (int i = 0; i < 32; i++)
        #pragma unroll
        for (int q = 0; q < 4; q++) oacc[i][q] = 0.f;
    float l0 = 0.f, l1 = 0.f;   // per-thread partial row sums

    for (int it = 0; it < FA_IT; it++) {
        // ---- wait Q/K_it (V_it may still be in flight) ----
        cpa_wait<1>();
        __syncthreads();

        // ---- S = Q K^T over D=256 ----
        float sacc[16][4];
        #pragma unroll
        for (int i = 0; i < 16; i++)
            #pragma unroll
            for (int q = 0; q < 4; q++) sacc[i][q] = 0.f;

        #pragma unroll
        for (int ks = 0; ks < 16; ks++) {
            uint32_t a[4];
            ldsm_x4(a, qbase + ks * 16);
            #pragma unroll
            for (int j = 0; j < 8; j++) {
                uint32_t bf4[4];
                ldsm_x4(bf4, kbase + j * 16 * QSTR + ks * 16);
                mma_bf16(sacc[2 * j],     a[0], a[1], a[2], a[3], bf4[0], bf4[1]);
                mma_bf16(sacc[2 * j + 1], a[0], a[1], a[2], a[3], bf4[2], bf4[3]);
            }
        }
        __syncthreads();   // all warps done reading sK

        // ---- prefetch K_{it+1} ----
        if (it + 1 < FA_IT) {
            fa_load_qk(sK, Kb + (size_t)(it + 1) * FA_BN * FA_D, tid);
            cpa_commit();
        }

        // ---- exp for first PV chunk (hides under the V wait) ----
        uint32_t pk[16][2];
        fa_expfrag(sacc[0], pk[0], l0, l1);
        fa_expfrag(sacc[1], pk[1], l0, l1);

        // ---- wait V_it ----
        if (it + 1 < FA_IT) cpa_wait<1>(); else cpa_wait<0>();
        __syncthreads();

        // ---- O += P @ V, exp(next chunk) interleaved with MMA(this chunk) --
        #pragma unroll
        for (int kk = 0; kk < 8; kk++) {
            uint32_t a0 = pk[2 * kk][0];
            uint32_t a1 = pk[2 * kk][1];
            uint32_t a2 = pk[2 * kk + 1][0];
            uint32_t a3 = pk[2 * kk + 1][1];
            if (kk < 7) {
                fa_expfrag(sacc[2 * kk + 2], pk[2 * kk + 2], l0, l1);
                fa_expfrag(sacc[2 * kk + 3], pk[2 * kk + 3], l0, l1);
            }
            #pragma unroll
            for (int j = 0; j < 16; j++) {
                uint32_t bf4[4];
                ldsm_x4(bf4, vbase + j * 16 * VSTR + kk * 16);
                mma_bf16(oacc[2 * j],     a0, a1, a2, a3, bf4[0], bf4[1]);
                mma_bf16(oacc[2 * j + 1], a0, a1, a2, a3, bf4[2], bf4[3]);
            }
        }
        __syncthreads();   // all warps done reading sV

        // ---- prefetch V_{it+1} ----
        if (it + 1 < FA_IT) {
            fa_load_v(sV, Vb + (size_t)(it + 1) * FA_BN, tid);
            cpa_commit();
        }
    }

    // ---- epilogue: reduce l across the quad (tig lanes), O /= l, store ----
    l0 += __shfl_xor_sync(0xffffffffu, l0, 1);
    l0 += __shfl_xor_sync(0xffffffffu, l0, 2);
    l1 += __shfl_xor_sync(0xffffffffu, l1, 1);
    l1 += __shfl_xor_sync(0xffffffffu, l1, 2);
    float i0 = 1.f / l0, i1 = 1.f / l1;
    bf16* orow = Og + ((size_t)b * NTOK + (size_t)qblk * FA_BM + r0) * FA_D;
    #pragma unroll
    for (int ni = 0; ni < 32; ni++) {
        int c = ni * 8 + tig * 2;
        *(__nv_bfloat162*)(orow + c) =
            __floats2bfloat162_rn(oacc[ni][0] * i0, oacc[ni][1] * i0);
        *(__nv_bfloat162*)(orow + (size_t)8 * FA_D + c) =
            __floats2bfloat162_rn(oacc[ni][2] * i1, oacc[ni][3] * i1);
    }
}

// ---------------- launcher ---------------------------------------------------
extern "C" void kernel_launch(void* const* d_in, const int* in_sizes, int n_in,
                              void* d_out, int out_size) {
    const float* x   = (const float*)d_in[0];
    const float* gns = (const float*)d_in[1];
    const float* gnb = (const float*)d_in[2];
    const float* wq  = (const float*)d_in[3];
    const float* bq  = (const float*)d_in[4];
    const float* wk  = (const float*)d_in[5];
    const float* bk  = (const float*)d_in[6];
    const float* wv  = (const float*)d_in[7];
    const float* bv  = (const float*)d_in[8];
    const float* wp  = (const float*)d_in[9];
    const float* bp  = (const float*)d_in[10];
    float* out = (float*)d_out;

    bf16 *p_h, *p_q, *p_k, *p_vT, *p_att, *p_w;
    cudaGetSymbolAddress((void**)&p_h,   g_h);
    cudaGetSymbolAddress((void**)&p_q,   g_q);
    cudaGetSymbolAddress((void**)&p_k,   g_k);
    cudaGetSymbolAddress((void**)&p_vT,  g_vT);
    cudaGetSymbolAddress((void**)&p_att, g_att);
    cudaGetSymbolAddress((void**)&p_w,   g_w);

    const size_t sNC = (size_t)NTOK * CH;
    const size_t sCN = (size_t)CH * NTOK;

    const int fa_smem = (FA_BM * QSTR + FA_BM * QSTR + FA_D * VSTR) * (int)sizeof(bf16);
    cudaFuncSetAttribute(fa_kernel, cudaFuncAttributeMaxDynamicSharedMemorySize, fa_smem);
    cudaFuncSetAttribute(gemm_tn, cudaFuncAttributeMaxDynamicSharedMemorySize, GEMM_SMEM);

    // 1) GroupNorm
    gn_stats<<<BATCH * NG, 256>>>(x);
    gn_apply<<<dim3(NTOK / 32, CH / 32, BATCH), dim3(32, 8)>>>(x, gns, gnb);
    conv_w<<<(CH * CH + 255) / 256, 256>>>(wq, wk, wv, wp);

    // 2) Q, K (row-major [N,C]) and V (col-major -> [C,N])
    dim3 gproj(CH / TBN, NTOK / TBM, BATCH);
    gemm_tn<<<gproj, 256, GEMM_SMEM>>>(p_h, p_w,               p_q,  nullptr, bq, nullptr,
                            1.f, NTOK, CH, CH, sNC, 0, sNC, 0, CH,   MODE_ROW);
    gemm_tn<<<gproj, 256, GEMM_SMEM>>>(p_h, p_w + CH * CH,     p_k,  nullptr, bk, nullptr,
                            1.f, NTOK, CH, CH, sNC, 0, sNC, 0, CH,   MODE_ROW);
    gemm_tn<<<gproj, 256, GEMM_SMEM>>>(p_h, p_w + 2 * CH * CH, p_vT, nullptr, bv, nullptr,
                            1.f, NTOK, CH, CH, sNC, 0, sCN, 0, NTOK, MODE_COL);

    // 3) fused attention: softmax(QK^T * C^-0.5) @ V  -> g_att [b][n][c]
    fa_kernel<<<dim3(NTOK / FA_BM, BATCH), 256, fa_smem>>>(p_q, p_k, p_vT, p_att);

    // 4) out = x + hatt @ wp^T + bp   (store transposed into [b][c][n] fp32)
    gemm_tn<<<dim3(CH / TBN, NTOK / TBM, BATCH), 256, GEMM_SMEM>>>(
        p_att, p_w + 3 * CH * CH, nullptr, out, bp, x,
        1.f, NTOK, CH, CH, sNC, 0, sCN, sCN, NTOK, MODE_RES);
}